// round 1
// baseline (speedup 1.0000x reference)
#include <cuda_runtime.h>
#include <math.h>

#define BATCH 2
#define SEQ   2048
#define HID   1024
#define NH    16
#define HD    64
#define MTOT  (BATCH*SEQ)   // 4096

// Scratch (device globals — no runtime allocation allowed)
__device__ float g_Q[BATCH*NH*SEQ*HD];     // [b,h,s,d]
__device__ float g_K[BATCH*NH*SEQ*HD];
__device__ float g_V[BATCH*NH*SEQ*HD];
__device__ float g_CTX[MTOT*HID];          // [b*s, h*64+d]

// ---------------------------------------------------------------------------
// Tiled GEMM: Y = X @ W^T + bias
// X: [MTOT, HID] row-major, W: [HID, HID] row-major (torch Linear layout: W[n,k])
// split_heads=1: write Y[m, n] -> out[((b*NH+h)*SEQ+s)*HD + d]  (b=m/SEQ, h=n/HD)
// split_heads=0: write Y[m, n] -> out[m*HID + n]
// ---------------------------------------------------------------------------
#define BM 64
#define BN 64
#define BK 16

__global__ __launch_bounds__(256) void gemm_bias_kernel(
    const float* __restrict__ X, const float* __restrict__ W,
    const float* __restrict__ bias, float* __restrict__ Y, int split_heads)
{
    __shared__ float Xs[BK][BM + 1];
    __shared__ float Ws[BK][BN + 1];

    const int tid = threadIdx.x;
    const int tx = tid & 15;        // 0..15
    const int ty = tid >> 4;        // 0..15
    const int m0 = blockIdx.y * BM;
    const int n0 = blockIdx.x * BN;

    float acc[4][4] = {};

    for (int k0 = 0; k0 < HID; k0 += BK) {
        #pragma unroll
        for (int i = tid; i < BM * BK; i += 256) {
            int kk = i & (BK - 1);
            int mm = i >> 4;
            Xs[kk][mm] = X[(m0 + mm) * HID + k0 + kk];
            Ws[kk][mm] = W[(n0 + mm) * HID + k0 + kk];
        }
        __syncthreads();

        #pragma unroll
        for (int kk = 0; kk < BK; kk++) {
            float a[4], b[4];
            #pragma unroll
            for (int i = 0; i < 4; i++) a[i] = Xs[kk][ty * 4 + i];
            #pragma unroll
            for (int j = 0; j < 4; j++) b[j] = Ws[kk][tx * 4 + j];
            #pragma unroll
            for (int i = 0; i < 4; i++)
                #pragma unroll
                for (int j = 0; j < 4; j++)
                    acc[i][j] = fmaf(a[i], b[j], acc[i][j]);
        }
        __syncthreads();
    }

    #pragma unroll
    for (int i = 0; i < 4; i++) {
        int m = m0 + ty * 4 + i;
        #pragma unroll
        for (int j = 0; j < 4; j++) {
            int n = n0 + tx * 4 + j;
            float v = acc[i][j] + bias[n];
            if (split_heads) {
                int b = m / SEQ, s = m % SEQ;
                int h = n / HD,  d = n % HD;
                Y[(((size_t)b * NH + h) * SEQ + s) * HD + d] = v;
            } else {
                Y[(size_t)m * HID + n] = v;
            }
        }
    }
}

// ---------------------------------------------------------------------------
// Flash attention (fp32, full softmax, no mask)
// grid: (SEQ/AM, BATCH*NH), 256 threads
// ---------------------------------------------------------------------------
#define AM 64     // query rows per block
#define AN 32     // key cols per tile

__global__ __launch_bounds__(256) void attn_kernel(float* __restrict__ ctx)
{
    __shared__ float Qs[AM][HD + 1];
    __shared__ float Ks[AN][HD + 1];
    __shared__ float Vs[AN][HD];
    __shared__ float Ps[AM][AN + 1];
    __shared__ float m_s[AM], l_s[AM], al_s[AM];

    const int tid = threadIdx.x;
    const int tx = tid & 15;
    const int ty = tid >> 4;
    const int bh = blockIdx.y;           // 0..31
    const int q0 = blockIdx.x * AM;

    const float* Qg = g_Q + (size_t)bh * SEQ * HD;
    const float* Kg = g_K + (size_t)bh * SEQ * HD;
    const float* Vg = g_V + (size_t)bh * SEQ * HD;

    // load Q tile, pre-scaled by 1/sqrt(64)
    for (int i = tid; i < AM * HD; i += 256) {
        int r = i >> 6, c = i & 63;
        Qs[r][c] = Qg[(size_t)(q0 + r) * HD + c] * 0.125f;
    }
    if (tid < AM) { m_s[tid] = -1e30f; l_s[tid] = 0.0f; }

    float o[4][4] = {};
    __syncthreads();

    for (int k0 = 0; k0 < SEQ; k0 += AN) {
        // load K/V tiles
        for (int i = tid; i < AN * HD; i += 256) {
            int r = i >> 6, c = i & 63;
            Ks[r][c] = Kg[(size_t)(k0 + r) * HD + c];
            Vs[r][c] = Vg[(size_t)(k0 + r) * HD + c];
        }
        __syncthreads();

        // scores: each thread 4 rows x 2 cols
        float s[4][2] = {};
        #pragma unroll
        for (int kk = 0; kk < HD; kk++) {
            float a[4], b[2];
            #pragma unroll
            for (int i = 0; i < 4; i++) a[i] = Qs[ty * 4 + i][kk];
            #pragma unroll
            for (int j = 0; j < 2; j++) b[j] = Ks[tx * 2 + j][kk];
            #pragma unroll
            for (int i = 0; i < 4; i++)
                #pragma unroll
                for (int j = 0; j < 2; j++)
                    s[i][j] = fmaf(a[i], b[j], s[i][j]);
        }
        #pragma unroll
        for (int i = 0; i < 4; i++)
            #pragma unroll
            for (int j = 0; j < 2; j++)
                Ps[ty * 4 + i][tx * 2 + j] = s[i][j];
        __syncthreads();

        // online softmax per row (threads 0..63)
        if (tid < AM) {
            float mo = m_s[tid];
            float mx = mo;
            #pragma unroll
            for (int c = 0; c < AN; c++) mx = fmaxf(mx, Ps[tid][c]);
            float al = __expf(mo - mx);
            float sum = 0.0f;
            #pragma unroll
            for (int c = 0; c < AN; c++) {
                float p = __expf(Ps[tid][c] - mx);
                Ps[tid][c] = p;
                sum += p;
            }
            m_s[tid] = mx;
            l_s[tid] = l_s[tid] * al + sum;
            al_s[tid] = al;
        }
        __syncthreads();

        // rescale accumulator + O += P @ V
        #pragma unroll
        for (int i = 0; i < 4; i++) {
            float a = al_s[ty * 4 + i];
            #pragma unroll
            for (int j = 0; j < 4; j++) o[i][j] *= a;
        }
        #pragma unroll
        for (int kk = 0; kk < AN; kk++) {
            float p[4], v[4];
            #pragma unroll
            for (int i = 0; i < 4; i++) p[i] = Ps[ty * 4 + i][kk];
            #pragma unroll
            for (int j = 0; j < 4; j++) v[j] = Vs[kk][tx * 4 + j];
            #pragma unroll
            for (int i = 0; i < 4; i++)
                #pragma unroll
                for (int j = 0; j < 4; j++)
                    o[i][j] = fmaf(p[i], v[j], o[i][j]);
        }
        __syncthreads();
    }

    // normalize + write back to [b*s, h*64+d] layout
    const int b = bh / NH, h = bh % NH;
    #pragma unroll
    for (int i = 0; i < 4; i++) {
        int lr = ty * 4 + i;
        float inv = 1.0f / l_s[lr];
        int srow = q0 + lr;
        #pragma unroll
        for (int j = 0; j < 4; j++) {
            ctx[((size_t)b * SEQ + srow) * HID + h * HD + tx * 4 + j] = o[i][j] * inv;
        }
    }
}

// ---------------------------------------------------------------------------
extern "C" void kernel_launch(void* const* d_in, const int* in_sizes, int n_in,
                              void* d_out, int out_size)
{
    const float* query = (const float*)d_in[0];
    const float* key   = (const float*)d_in[1];
    const float* value = (const float*)d_in[2];
    const float* Wq = (const float*)d_in[3];
    const float* bq = (const float*)d_in[4];
    const float* Wk = (const float*)d_in[5];
    const float* bk = (const float*)d_in[6];
    const float* Wv = (const float*)d_in[7];
    const float* bv = (const float*)d_in[8];
    const float* Wo = (const float*)d_in[9];
    const float* bo = (const float*)d_in[10];
    float* out = (float*)d_out;

    float *qbuf, *kbuf, *vbuf, *cbuf;
    cudaGetSymbolAddress((void**)&qbuf, g_Q);
    cudaGetSymbolAddress((void**)&kbuf, g_K);
    cudaGetSymbolAddress((void**)&vbuf, g_V);
    cudaGetSymbolAddress((void**)&cbuf, g_CTX);

    dim3 ggrid(HID / BN, MTOT / BM);
    gemm_bias_kernel<<<ggrid, 256>>>(query, Wq, bq, qbuf, 1);
    gemm_bias_kernel<<<ggrid, 256>>>(key,   Wk, bk, kbuf, 1);
    gemm_bias_kernel<<<ggrid, 256>>>(value, Wv, bv, vbuf, 1);

    dim3 agrid(SEQ / AM, BATCH * NH);
    attn_kernel<<<agrid, 256>>>(cbuf);

    gemm_bias_kernel<<<ggrid, 256>>>(cbuf, Wo, bo, out, 0);
}

// round 6
// speedup vs baseline: 1.8775x; 1.8775x over previous
#include <cuda_runtime.h>
#include <cuda_bf16.h>
#include <cstdint>
#include <math.h>

#define BATCH 2
#define SEQ   2048
#define HID   1024
#define NH    16
#define HD    64
#define MTOT  (BATCH*SEQ)   // 4096
#define KS    (3*HID)       // 3072 : [hi | hi | lo] x [hi | lo | hi]

// ---------------- static scratch (no runtime allocation allowed) ------------
__device__ __align__(16) __nv_bfloat16 g_A[(size_t)MTOT * KS];   // 24 MB, reused per GEMM
__device__ __align__(16) __nv_bfloat16 g_B[(size_t)HID * KS];    // 6 MB, reused per GEMM
__device__ float g_Q  [(size_t)BATCH*NH*SEQ*HD];
__device__ float g_Kb [(size_t)BATCH*NH*SEQ*HD];
__device__ float g_V  [(size_t)BATCH*NH*SEQ*HD];
__device__ float g_CTX[(size_t)MTOT*HID];

// ---------------- helpers ---------------------------------------------------
__device__ __forceinline__ uint32_t smem_u32(const void* p) {
    uint32_t a;
    asm("{ .reg .u64 t; cvta.to.shared.u64 t, %1; cvt.u32.u64 %0, t; }" : "=r"(a) : "l"(p));
    return a;
}
#define CP_ASYNC16(dst, src) \
    asm volatile("cp.async.cg.shared.global [%0], [%1], 16;" :: "r"(dst), "l"(src))
#define CP_COMMIT()  asm volatile("cp.async.commit_group;" ::: "memory")
#define CP_WAIT0()   asm volatile("cp.async.wait_group 0;" ::: "memory")
#define CP_WAIT1()   asm volatile("cp.async.wait_group 1;" ::: "memory")

__device__ __forceinline__ void ldm_x4(uint32_t* f, uint32_t addr) {
    asm volatile("ldmatrix.sync.aligned.m8n8.x4.shared.b16 {%0,%1,%2,%3}, [%4];"
        : "=r"(f[0]), "=r"(f[1]), "=r"(f[2]), "=r"(f[3]) : "r"(addr));
}
__device__ __forceinline__ void mma_bf16(float* d, const uint32_t* a, const uint32_t* b) {
    asm volatile("mma.sync.aligned.m16n8k16.row.col.f32.bf16.bf16.f32 "
        "{%0,%1,%2,%3}, {%4,%5,%6,%7}, {%8,%9}, {%0,%1,%2,%3};"
        : "+f"(d[0]), "+f"(d[1]), "+f"(d[2]), "+f"(d[3])
        : "r"(a[0]), "r"(a[1]), "r"(a[2]), "r"(a[3]), "r"(b[0]), "r"(b[1]));
}

// ---------------------------------------------------------------------------
// Split kernel: fp32 [nrows, 1024] -> bf16 [nrows, 3072] (segments)
// bmode=0 (A-style): [hi | hi | lo];  bmode=1 (B-style): [hi | lo | hi]
// ---------------------------------------------------------------------------
__global__ __launch_bounds__(256) void split_kernel(
    const float* __restrict__ X, __nv_bfloat16* __restrict__ out, int nrows, int bmode)
{
    int idx = blockIdx.x * 256 + threadIdx.x;
    int total = nrows * (HID / 2);
    if (idx >= total) return;
    int row = idx >> 9;
    int c2 = (idx & 511) * 2;
    float2 x = *(const float2*)(X + (size_t)row * HID + c2);
    __nv_bfloat16 h0 = __float2bfloat16(x.x), h1 = __float2bfloat16(x.y);
    float r0 = x.x - __bfloat162float(h0);
    float r1 = x.y - __bfloat162float(h1);
    __nv_bfloat162 hi, lo;
    hi.x = h0; hi.y = h1;
    lo.x = __float2bfloat16(r0); lo.y = __float2bfloat16(r1);
    __nv_bfloat162* o = (__nv_bfloat162*)(out + (size_t)row * KS + c2);
    o[0] = hi;
    if (bmode == 0) { o[512] = hi; o[1024] = lo; }
    else            { o[512] = lo; o[1024] = hi; }
}

// ---------------------------------------------------------------------------
// Warp-MMA bf16 GEMM: C[M,N] = A''[M,3072] @ B''[N,3072]^T + bias
// Block tile 128x128, BK=64, 8 warps (2x4), warp tile 64x32.
// Fragments via ldmatrix from SW128-swizzled smem; cp.async double buffer.
// ---------------------------------------------------------------------------
#define GM 128
#define GN 128
#define GK 64
#define NKC (KS / GK)     // 48
#define SMEM_GEMM (4 * 16384)   // 2 stages x (A 16KB + B 16KB)

__global__ __launch_bounds__(256) void gemm_mma_kernel(
    const __nv_bfloat16* __restrict__ A, const __nv_bfloat16* __restrict__ B,
    const float* __restrict__ bias, float* __restrict__ out, int split_heads)
{
    extern __shared__ char smem[];
    const uint32_t sb = smem_u32(smem);
    const int tid  = threadIdx.x;
    const int wid  = tid >> 5;
    const int lane = tid & 31;
    const int warp_m = wid & 1;        // 0..1  (64 rows each)
    const int warp_n = wid >> 1;       // 0..3  (32 cols each)
    const int m0 = blockIdx.y * GM;
    const int n0 = blockIdx.x * GN;

    // stage offsets: A then B per stage
    const uint32_t TA[2] = {sb,             sb + 32768};
    const uint32_t TB[2] = {sb + 16384,     sb + 49152};

    const char* Abase = (const char*)(A + (size_t)m0 * KS);
    const char* Bbase = (const char*)(B + (size_t)n0 * KS);

    // cp.async one K-chunk (A 128x64 bf16 + B 128x64 bf16) into stage st
    auto load_chunk = [&](int st, int kc) {
        const char* Ap = Abase + (size_t)kc * (GK * 2);
        const char* Bp = Bbase + (size_t)kc * (GK * 2);
        #pragma unroll
        for (int i = 0; i < 4; i++) {
            int cid = tid + i * 256;          // 0..1023
            int row = cid >> 3, c16 = cid & 7;
            uint32_t off = row * 128 + c16 * 16;
            off ^= ((off >> 3) & 0x70);       // SW128-style swizzle (chunk ^= row&7)
            CP_ASYNC16(TA[st] + off, Ap + (size_t)row * (KS * 2) + c16 * 16);
            CP_ASYNC16(TB[st] + off, Bp + (size_t)row * (KS * 2) + c16 * 16);
        }
        CP_COMMIT();
    };

    // ldmatrix per-lane addressing (swizzled)
    const int g = lane >> 3, r = lane & 7;
    const uint32_t a_row = warp_m * 64 + (g & 1) * 8 + r;      // + mt*16
    const int a_kg = g >> 1;                                   // k-chunk offset 0/1
    const uint32_t b_row = warp_n * 32 + (g >> 1) * 8 + r;     // + nt2*16
    const int b_kg = g & 1;

    float acc[4][4][4] = {};   // [mt][nt][reg]

    load_chunk(0, 0);

    for (int kc = 0; kc < NKC; kc++) {
        int cur = kc & 1;
        if (kc + 1 < NKC) { load_chunk(1 - cur, kc + 1); CP_WAIT1(); }
        else              { CP_WAIT0(); }
        __syncthreads();

        const uint32_t Asm = TA[cur] + a_row * 128;
        const uint32_t Bsm = TB[cur] + b_row * 128;

        #pragma unroll
        for (int ks = 0; ks < 4; ks++) {
            uint32_t af[4][4];
            #pragma unroll
            for (int mt = 0; mt < 4; mt++)
                ldm_x4(af[mt], Asm + mt * 2048 + (((ks * 2 + a_kg) ^ r) << 4));
            uint32_t bf[4][2];
            #pragma unroll
            for (int nt2 = 0; nt2 < 2; nt2++) {
                uint32_t t[4];
                ldm_x4(t, Bsm + nt2 * 2048 + (((ks * 2 + b_kg) ^ r) << 4));
                bf[nt2 * 2 + 0][0] = t[0]; bf[nt2 * 2 + 0][1] = t[1];
                bf[nt2 * 2 + 1][0] = t[2]; bf[nt2 * 2 + 1][1] = t[3];
            }
            #pragma unroll
            for (int mt = 0; mt < 4; mt++)
                #pragma unroll
                for (int nt = 0; nt < 4; nt++)
                    mma_bf16(acc[mt][nt], af[mt], bf[nt]);
        }
        __syncthreads();
    }

    // epilogue: d0,d1 -> (row, col), (row, col+1); d2,d3 -> (row+8, ...)
    const int mrow = m0 + warp_m * 64 + (lane >> 2);
    const int ncol = n0 + warp_n * 32 + (lane & 3) * 2;
    #pragma unroll
    for (int mt = 0; mt < 4; mt++) {
        #pragma unroll
        for (int nt = 0; nt < 4; nt++) {
            int n = ncol + nt * 8;
            float b0 = __ldg(bias + n), b1 = __ldg(bias + n + 1);
            #pragma unroll
            for (int half = 0; half < 2; half++) {
                int m = mrow + mt * 16 + half * 8;
                float v0 = acc[mt][nt][half * 2 + 0] + b0;
                float v1 = acc[mt][nt][half * 2 + 1] + b1;
                float* dst;
                if (split_heads) {
                    int b = m / SEQ, s = m % SEQ;
                    int h = n >> 6, d0 = n & 63;
                    dst = out + (((size_t)b * NH + h) * SEQ + s) * HD + d0;
                } else {
                    dst = out + (size_t)m * HID + n;
                }
                dst[0] = v0; dst[1] = v1;
            }
        }
    }
}

// ---------------------------------------------------------------------------
// Flash attention (fp32), softmax parallelized over 256 threads
// ---------------------------------------------------------------------------
#define AM 64
#define AN 32

__global__ __launch_bounds__(256) void attn_kernel(float* __restrict__ ctx)
{
    __shared__ float Qs[AM][HD + 1];
    __shared__ float Ks2[AN][HD + 1];
    __shared__ float Vs[AN][HD];
    __shared__ float Ps[AM][AN + 1];
    __shared__ float m_s[AM], l_s[AM], al_s[AM];

    const int tid = threadIdx.x;
    const int tx = tid & 15;
    const int ty = tid >> 4;
    const int bh = blockIdx.y;
    const int q0 = blockIdx.x * AM;

    const float* Qg = g_Q  + (size_t)bh * SEQ * HD;
    const float* Kg = g_Kb + (size_t)bh * SEQ * HD;
    const float* Vg = g_V  + (size_t)bh * SEQ * HD;

    for (int i = tid; i < AM * HD; i += 256) {
        int r = i >> 6, c = i & 63;
        Qs[r][c] = Qg[(size_t)(q0 + r) * HD + c] * 0.125f;
    }
    if (tid < AM) { m_s[tid] = -1e30f; l_s[tid] = 0.0f; }

    float o[4][4] = {};
    __syncthreads();

    for (int k0 = 0; k0 < SEQ; k0 += AN) {
        for (int i = tid; i < AN * HD; i += 256) {
            int r = i >> 6, c = i & 63;
            Ks2[r][c] = Kg[(size_t)(k0 + r) * HD + c];
            Vs[r][c]  = Vg[(size_t)(k0 + r) * HD + c];
        }
        __syncthreads();

        float s[4][2] = {};
        #pragma unroll
        for (int kk = 0; kk < HD; kk++) {
            float a[4], b[2];
            #pragma unroll
            for (int i = 0; i < 4; i++) a[i] = Qs[ty * 4 + i][kk];
            #pragma unroll
            for (int j = 0; j < 2; j++) b[j] = Ks2[tx * 2 + j][kk];
            #pragma unroll
            for (int i = 0; i < 4; i++)
                #pragma unroll
                for (int j = 0; j < 2; j++)
                    s[i][j] = fmaf(a[i], b[j], s[i][j]);
        }
        #pragma unroll
        for (int i = 0; i < 4; i++)
            #pragma unroll
            for (int j = 0; j < 2; j++)
                Ps[ty * 4 + i][tx * 2 + j] = s[i][j];
        __syncthreads();

        // online softmax: row r handled by 4 threads (8 cols each)
        {
            int rr = tid >> 2, gg = tid & 3;
            float mo = m_s[rr];
            float mx = mo;
            #pragma unroll
            for (int c = 0; c < 8; c++) mx = fmaxf(mx, Ps[rr][gg * 8 + c]);
            mx = fmaxf(mx, __shfl_xor_sync(0xffffffffu, mx, 1));
            mx = fmaxf(mx, __shfl_xor_sync(0xffffffffu, mx, 2));
            float sum = 0.0f;
            #pragma unroll
            for (int c = 0; c < 8; c++) {
                float p = __expf(Ps[rr][gg * 8 + c] - mx);
                Ps[rr][gg * 8 + c] = p;
                sum += p;
            }
            sum += __shfl_xor_sync(0xffffffffu, sum, 1);
            sum += __shfl_xor_sync(0xffffffffu, sum, 2);
            __syncwarp();
            if (gg == 0) {
                float al = __expf(mo - mx);
                m_s[rr] = mx;
                l_s[rr] = l_s[rr] * al + sum;
                al_s[rr] = al;
            }
        }
        __syncthreads();

        #pragma unroll
        for (int i = 0; i < 4; i++) {
            float a = al_s[ty * 4 + i];
            #pragma unroll
            for (int j = 0; j < 4; j++) o[i][j] *= a;
        }
        #pragma unroll
        for (int kk = 0; kk < AN; kk++) {
            float p[4], v[4];
            #pragma unroll
            for (int i = 0; i < 4; i++) p[i] = Ps[ty * 4 + i][kk];
            #pragma unroll
            for (int j = 0; j < 4; j++) v[j] = Vs[kk][tx * 4 + j];
            #pragma unroll
            for (int i = 0; i < 4; i++)
                #pragma unroll
                for (int j = 0; j < 4; j++)
                    o[i][j] = fmaf(p[i], v[j], o[i][j]);
        }
        __syncthreads();
    }

    const int b = bh / NH, h = bh % NH;
    #pragma unroll
    for (int i = 0; i < 4; i++) {
        int lr = ty * 4 + i;
        float inv = 1.0f / l_s[lr];
        int srow = q0 + lr;
        #pragma unroll
        for (int j = 0; j < 4; j++)
            ctx[((size_t)b * SEQ + srow) * HID + h * HD + tx * 4 + j] = o[i][j] * inv;
    }
}

// ---------------------------------------------------------------------------
extern "C" void kernel_launch(void* const* d_in, const int* in_sizes, int n_in,
                              void* d_out, int out_size)
{
    const float* query = (const float*)d_in[0];
    const float* key   = (const float*)d_in[1];
    const float* value = (const float*)d_in[2];
    const float* Wq = (const float*)d_in[3];
    const float* bq = (const float*)d_in[4];
    const float* Wk = (const float*)d_in[5];
    const float* bk = (const float*)d_in[6];
    const float* Wv = (const float*)d_in[7];
    const float* bv = (const float*)d_in[8];
    const float* Wo = (const float*)d_in[9];
    const float* bo = (const float*)d_in[10];
    float* out = (float*)d_out;

    __nv_bfloat16 *abuf, *bbuf;
    float *qbuf, *kbuf, *vbuf, *cbuf;
    cudaGetSymbolAddress((void**)&abuf, g_A);
    cudaGetSymbolAddress((void**)&bbuf, g_B);
    cudaGetSymbolAddress((void**)&qbuf, g_Q);
    cudaGetSymbolAddress((void**)&kbuf, g_Kb);
    cudaGetSymbolAddress((void**)&vbuf, g_V);
    cudaGetSymbolAddress((void**)&cbuf, g_CTX);

    cudaFuncSetAttribute(gemm_mma_kernel,
                         cudaFuncAttributeMaxDynamicSharedMemorySize, SMEM_GEMM);

    const int splitA_blocks = MTOT * (HID / 2) / 256;   // 8192
    const int splitB_blocks = HID * (HID / 2) / 256;    // 2048
    dim3 ggrid(HID / GN, MTOT / GM);                    // (8, 32)

    // Q projection
    split_kernel<<<splitA_blocks, 256>>>(query, abuf, MTOT, 0);
    split_kernel<<<splitB_blocks, 256>>>(Wq, bbuf, HID, 1);
    gemm_mma_kernel<<<ggrid, 256, SMEM_GEMM>>>(abuf, bbuf, bq, qbuf, 1);
    // K projection
    split_kernel<<<splitA_blocks, 256>>>(key, abuf, MTOT, 0);
    split_kernel<<<splitB_blocks, 256>>>(Wk, bbuf, HID, 1);
    gemm_mma_kernel<<<ggrid, 256, SMEM_GEMM>>>(abuf, bbuf, bk, kbuf, 1);
    // V projection
    split_kernel<<<splitA_blocks, 256>>>(value, abuf, MTOT, 0);
    split_kernel<<<splitB_blocks, 256>>>(Wv, bbuf, HID, 1);
    gemm_mma_kernel<<<ggrid, 256, SMEM_GEMM>>>(abuf, bbuf, bv, vbuf, 1);

    // attention
    dim3 agrid(SEQ / AM, BATCH * NH);
    attn_kernel<<<agrid, 256>>>(cbuf);

    // output projection
    split_kernel<<<splitA_blocks, 256>>>(cbuf, abuf, MTOT, 0);
    split_kernel<<<splitB_blocks, 256>>>(Wo, bbuf, HID, 1);
    gemm_mma_kernel<<<ggrid, 256, SMEM_GEMM>>>(abuf, bbuf, bo, out, 0);
}

// round 7
// speedup vs baseline: 3.8557x; 2.0537x over previous
#include <cuda_runtime.h>
#include <cuda_bf16.h>
#include <cstdint>
#include <math.h>

#define BATCH 2
#define SEQ   2048
#define HID   1024
#define NH    16
#define HD    64
#define MTOT  (BATCH*SEQ)   // 4096
#define KS    (3*HID)       // 3072 : [hi | hi | lo] x [hi | lo | hi]

// ---------------- static scratch (no runtime allocation allowed) ------------
__device__ __align__(16) __nv_bfloat16 g_A[(size_t)MTOT * KS];   // 24 MB
__device__ __align__(16) __nv_bfloat16 g_B[(size_t)HID * KS];    // 6 MB
__device__ __align__(16) __nv_bfloat16 g_Qh[(size_t)BATCH*NH*SEQ*HD];
__device__ __align__(16) __nv_bfloat16 g_Ql[(size_t)BATCH*NH*SEQ*HD];
__device__ __align__(16) __nv_bfloat16 g_Kh[(size_t)BATCH*NH*SEQ*HD];
__device__ __align__(16) __nv_bfloat16 g_Kl[(size_t)BATCH*NH*SEQ*HD];
__device__ __align__(16) __nv_bfloat16 g_Vh[(size_t)BATCH*NH*SEQ*HD];
__device__ __align__(16) __nv_bfloat16 g_Vl[(size_t)BATCH*NH*SEQ*HD];
__device__ float g_CTX[(size_t)MTOT*HID];

// ---------------- helpers ---------------------------------------------------
__device__ __forceinline__ uint32_t smem_u32(const void* p) {
    uint32_t a;
    asm("{ .reg .u64 t; cvta.to.shared.u64 t, %1; cvt.u32.u64 %0, t; }" : "=r"(a) : "l"(p));
    return a;
}
#define CP_ASYNC16(dst, src) \
    asm volatile("cp.async.cg.shared.global [%0], [%1], 16;" :: "r"(dst), "l"(src))
#define CP_COMMIT()  asm volatile("cp.async.commit_group;" ::: "memory")
#define CP_WAIT0()   asm volatile("cp.async.wait_group 0;" ::: "memory")
#define CP_WAIT1()   asm volatile("cp.async.wait_group 1;" ::: "memory")

__device__ __forceinline__ void ldm_x4(uint32_t* f, uint32_t addr) {
    asm volatile("ldmatrix.sync.aligned.m8n8.x4.shared.b16 {%0,%1,%2,%3}, [%4];"
        : "=r"(f[0]), "=r"(f[1]), "=r"(f[2]), "=r"(f[3]) : "r"(addr));
}
__device__ __forceinline__ void ldm_x4_t(uint32_t* f, uint32_t addr) {
    asm volatile("ldmatrix.sync.aligned.m8n8.x4.trans.shared.b16 {%0,%1,%2,%3}, [%4];"
        : "=r"(f[0]), "=r"(f[1]), "=r"(f[2]), "=r"(f[3]) : "r"(addr));
}
__device__ __forceinline__ void mma_bf16(float* d, const uint32_t* a, const uint32_t* b) {
    asm volatile("mma.sync.aligned.m16n8k16.row.col.f32.bf16.bf16.f32 "
        "{%0,%1,%2,%3}, {%4,%5,%6,%7}, {%8,%9}, {%0,%1,%2,%3};"
        : "+f"(d[0]), "+f"(d[1]), "+f"(d[2]), "+f"(d[3])
        : "r"(a[0]), "r"(a[1]), "r"(a[2]), "r"(a[3]), "r"(b[0]), "r"(b[1]));
}
// pack two fp32 -> bf16x2 (lo = first k element)
__device__ __forceinline__ uint32_t pack_bf2(float lo, float hi) {
    uint32_t r;
    asm("cvt.rn.bf16x2.f32 %0, %1, %2;" : "=r"(r) : "f"(hi), "f"(lo));
    return r;
}
// split (a,b) fp32 pair into bf16x2 hi + bf16x2 lo(residual)
__device__ __forceinline__ void split_pair(float a, float b, uint32_t& hi, uint32_t& lo) {
    __nv_bfloat16 ha = __float2bfloat16(a), hb = __float2bfloat16(b);
    hi = (uint32_t)__bfloat16_as_ushort(ha) | ((uint32_t)__bfloat16_as_ushort(hb) << 16);
    lo = pack_bf2(a - __bfloat162float(ha), b - __bfloat162float(hb));
}

// ---------------------------------------------------------------------------
// Split kernel: fp32 [nrows, 1024] -> bf16 [nrows, 3072] (segments)
// bmode=0 (A-style): [hi | hi | lo];  bmode=1 (B-style): [hi | lo | hi]
// ---------------------------------------------------------------------------
__global__ __launch_bounds__(256) void split_kernel(
    const float* __restrict__ X, __nv_bfloat16* __restrict__ out, int nrows, int bmode)
{
    int idx = blockIdx.x * 256 + threadIdx.x;
    int total = nrows * (HID / 2);
    if (idx >= total) return;
    int row = idx >> 9;
    int c2 = (idx & 511) * 2;
    float2 x = *(const float2*)(X + (size_t)row * HID + c2);
    __nv_bfloat16 h0 = __float2bfloat16(x.x), h1 = __float2bfloat16(x.y);
    float r0 = x.x - __bfloat162float(h0);
    float r1 = x.y - __bfloat162float(h1);
    __nv_bfloat162 hi, lo;
    hi.x = h0; hi.y = h1;
    lo.x = __float2bfloat16(r0); lo.y = __float2bfloat16(r1);
    __nv_bfloat162* o = (__nv_bfloat162*)(out + (size_t)row * KS + c2);
    o[0] = hi;
    if (bmode == 0) { o[512] = hi; o[1024] = lo; }
    else            { o[512] = lo; o[1024] = hi; }
}

// ---------------------------------------------------------------------------
// Warp-MMA bf16 GEMM: C[M,N] = A''[M,3072] @ B''[N,3072]^T + bias
// mode 0: fp32 dense out[m*HID+n]
// mode 1: bf16 hi/lo head-split out ([b,h,s,d]), value scaled by `scale`
// ---------------------------------------------------------------------------
#define GM 128
#define GN 128
#define GK 64
#define NKC (KS / GK)     // 48
#define SMEM_GEMM (4 * 16384)

__global__ __launch_bounds__(256) void gemm_mma_kernel(
    const __nv_bfloat16* __restrict__ A, const __nv_bfloat16* __restrict__ B,
    const float* __restrict__ bias, float* __restrict__ out,
    __nv_bfloat16* __restrict__ outh, __nv_bfloat16* __restrict__ outl,
    int mode, float scale)
{
    extern __shared__ char smem[];
    const uint32_t sb = smem_u32(smem);
    const int tid  = threadIdx.x;
    const int wid  = tid >> 5;
    const int lane = tid & 31;
    const int warp_m = wid & 1;
    const int warp_n = wid >> 1;
    const int m0 = blockIdx.y * GM;
    const int n0 = blockIdx.x * GN;

    const uint32_t TA[2] = {sb,         sb + 32768};
    const uint32_t TB[2] = {sb + 16384, sb + 49152};

    const char* Abase = (const char*)(A + (size_t)m0 * KS);
    const char* Bbase = (const char*)(B + (size_t)n0 * KS);

    auto load_chunk = [&](int st, int kc) {
        const char* Ap = Abase + (size_t)kc * (GK * 2);
        const char* Bp = Bbase + (size_t)kc * (GK * 2);
        #pragma unroll
        for (int i = 0; i < 4; i++) {
            int cid = tid + i * 256;
            int row = cid >> 3, c16 = cid & 7;
            uint32_t off = row * 128 + c16 * 16;
            off ^= ((off >> 3) & 0x70);
            CP_ASYNC16(TA[st] + off, Ap + (size_t)row * (KS * 2) + c16 * 16);
            CP_ASYNC16(TB[st] + off, Bp + (size_t)row * (KS * 2) + c16 * 16);
        }
        CP_COMMIT();
    };

    const int g = lane >> 3, r = lane & 7;
    const uint32_t a_row = warp_m * 64 + (g & 1) * 8 + r;
    const int a_kg = g >> 1;
    const uint32_t b_row = warp_n * 32 + (g >> 1) * 8 + r;
    const int b_kg = g & 1;

    float acc[4][4][4] = {};

    load_chunk(0, 0);

    for (int kc = 0; kc < NKC; kc++) {
        int cur = kc & 1;
        if (kc + 1 < NKC) { load_chunk(1 - cur, kc + 1); CP_WAIT1(); }
        else              { CP_WAIT0(); }
        __syncthreads();

        const uint32_t Asm = TA[cur] + a_row * 128;
        const uint32_t Bsm = TB[cur] + b_row * 128;

        #pragma unroll
        for (int ks = 0; ks < 4; ks++) {
            uint32_t af[4][4];
            #pragma unroll
            for (int mt = 0; mt < 4; mt++)
                ldm_x4(af[mt], Asm + mt * 2048 + (((ks * 2 + a_kg) ^ r) << 4));
            uint32_t bf[4][2];
            #pragma unroll
            for (int nt2 = 0; nt2 < 2; nt2++) {
                uint32_t t[4];
                ldm_x4(t, Bsm + nt2 * 2048 + (((ks * 2 + b_kg) ^ r) << 4));
                bf[nt2 * 2 + 0][0] = t[0]; bf[nt2 * 2 + 0][1] = t[1];
                bf[nt2 * 2 + 1][0] = t[2]; bf[nt2 * 2 + 1][1] = t[3];
            }
            #pragma unroll
            for (int mt = 0; mt < 4; mt++)
                #pragma unroll
                for (int nt = 0; nt < 4; nt++)
                    mma_bf16(acc[mt][nt], af[mt], bf[nt]);
        }
        __syncthreads();
    }

    const int mrow = m0 + warp_m * 64 + (lane >> 2);
    const int ncol = n0 + warp_n * 32 + (lane & 3) * 2;
    #pragma unroll
    for (int mt = 0; mt < 4; mt++) {
        #pragma unroll
        for (int nt = 0; nt < 4; nt++) {
            int n = ncol + nt * 8;
            float b0 = __ldg(bias + n), b1 = __ldg(bias + n + 1);
            #pragma unroll
            for (int half = 0; half < 2; half++) {
                int m = mrow + mt * 16 + half * 8;
                float v0 = acc[mt][nt][half * 2 + 0] + b0;
                float v1 = acc[mt][nt][half * 2 + 1] + b1;
                if (mode == 1) {
                    v0 *= scale; v1 *= scale;
                    int b = m / SEQ, s = m % SEQ;
                    int h = n >> 6, d0 = n & 63;
                    size_t idx = (((size_t)b * NH + h) * SEQ + s) * HD + d0;
                    __nv_bfloat16 h0 = __float2bfloat16(v0), h1 = __float2bfloat16(v1);
                    __nv_bfloat162 hi2, lo2;
                    hi2.x = h0; hi2.y = h1;
                    lo2.x = __float2bfloat16(v0 - __bfloat162float(h0));
                    lo2.y = __float2bfloat16(v1 - __bfloat162float(h1));
                    *(__nv_bfloat162*)(outh + idx) = hi2;
                    *(__nv_bfloat162*)(outl + idx) = lo2;
                } else {
                    float* dst = out + (size_t)m * HID + n;
                    dst[0] = v0; dst[1] = v1;
                }
            }
        }
    }
}

// ---------------------------------------------------------------------------
// Tensor-core flash attention (bf16 hi/lo, fp32 accum)
// block: 128 q-rows, 8 warps (16 rows each); k-tiles of 64 keys
// smem: 2 stages x (Khi,Klo,Vhi,Vlo 8KB each) = 64KB
// ---------------------------------------------------------------------------
#define SMEM_ATTN 65536

__global__ __launch_bounds__(256) void attn_mma_kernel(float* __restrict__ ctx)
{
    extern __shared__ char smem[];
    const uint32_t sb = smem_u32(smem);
    const int tid = threadIdx.x, warp = tid >> 5, lane = tid & 31;
    const int g = lane >> 3, r = lane & 7;
    const int bh = blockIdx.y;
    const int q0 = blockIdx.x * 128;

    const char* Qh = (const char*)(g_Qh + (size_t)bh * SEQ * HD);
    const char* Ql = (const char*)(g_Ql + (size_t)bh * SEQ * HD);
    const char* Kh = (const char*)(g_Kh + (size_t)bh * SEQ * HD);
    const char* Kl = (const char*)(g_Kl + (size_t)bh * SEQ * HD);
    const char* Vh = (const char*)(g_Vh + (size_t)bh * SEQ * HD);
    const char* Vl = (const char*)(g_Vl + (size_t)bh * SEQ * HD);

    // ---- load Q tile (128x64 hi + lo) into stage-0 area, build fragments ----
    {
        const char* srcs[2] = {Qh, Ql};
        #pragma unroll
        for (int i = 0; i < 8; i++) {
            int cid = tid + i * 256;          // 0..2047
            int arr = cid >> 10;
            int rem = cid & 1023;
            int row = rem >> 3, ch = rem & 7;
            uint32_t off = row * 128 + ((ch ^ (row & 7)) << 4);
            CP_ASYNC16(sb + arr * 16384 + off,
                       srcs[arr] + (size_t)(q0 + row) * 128 + ch * 16);
        }
        CP_COMMIT(); CP_WAIT0();
        __syncthreads();
    }
    uint32_t qf[2][4][4];
    #pragma unroll
    for (int seg = 0; seg < 2; seg++) {
        uint32_t base = sb + seg * 16384;
        #pragma unroll
        for (int ks = 0; ks < 4; ks++) {
            uint32_t row = warp * 16 + (g & 1) * 8 + r;
            ldm_x4(qf[seg][ks], base + row * 128 + (((ks * 2 + (g >> 1)) ^ r) << 4));
        }
    }
    __syncthreads();

    // ---- main loop over key tiles ----
    auto kvload = [&](int st, int kt) {
        uint32_t stb = sb + st * 32768;
        const char* srcs[4] = {Kh, Kl, Vh, Vl};
        #pragma unroll
        for (int i = 0; i < 8; i++) {
            int cid = tid + i * 256;          // 0..2047
            int arr = cid >> 9;
            int rem = cid & 511;
            int row = rem >> 3, ch = rem & 7;
            uint32_t off = row * 128 + ((ch ^ (row & 7)) << 4);
            CP_ASYNC16(stb + arr * 8192 + off,
                       srcs[arr] + (size_t)(kt * 64 + row) * 128 + ch * 16);
        }
        CP_COMMIT();
    };

    float oacc[8][4] = {};
    float m0 = -1e30f, m1 = -1e30f, l0 = 0.0f, l1 = 0.0f;

    kvload(0, 0);

    for (int kt = 0; kt < SEQ / 64; kt++) {
        int cur = kt & 1;
        if (kt + 1 < SEQ / 64) { kvload(1 - cur, kt + 1); CP_WAIT1(); }
        else                   { CP_WAIT0(); }
        __syncthreads();

        const uint32_t Khb = sb + cur * 32768;
        const uint32_t Klb = Khb + 8192;
        const uint32_t Vhb = Khb + 16384;
        const uint32_t Vlb = Khb + 24576;

        // ---- scores: S = Qhi Khi^T + Qlo Khi^T + Qhi Klo^T ----
        float sacc[8][4] = {};
        #pragma unroll
        for (int ks = 0; ks < 4; ks++) {
            #pragma unroll
            for (int nt2 = 0; nt2 < 4; nt2++) {
                uint32_t brow = nt2 * 16 + (g >> 1) * 8 + r;
                uint32_t koff = ((ks * 2 + (g & 1)) ^ r) << 4;
                uint32_t t[4];
                ldm_x4(t, Khb + brow * 128 + koff);
                mma_bf16(sacc[2 * nt2],     qf[0][ks], t + 0);
                mma_bf16(sacc[2 * nt2 + 1], qf[0][ks], t + 2);
                mma_bf16(sacc[2 * nt2],     qf[1][ks], t + 0);
                mma_bf16(sacc[2 * nt2 + 1], qf[1][ks], t + 2);
                uint32_t u[4];
                ldm_x4(u, Klb + brow * 128 + koff);
                mma_bf16(sacc[2 * nt2],     qf[0][ks], u + 0);
                mma_bf16(sacc[2 * nt2 + 1], qf[0][ks], u + 2);
            }
        }

        // ---- online softmax (rows r0 = regs 0,1 ; r1 = regs 2,3) ----
        float mx0 = m0, mx1 = m1;
        #pragma unroll
        for (int nt = 0; nt < 8; nt++) {
            mx0 = fmaxf(mx0, fmaxf(sacc[nt][0], sacc[nt][1]));
            mx1 = fmaxf(mx1, fmaxf(sacc[nt][2], sacc[nt][3]));
        }
        mx0 = fmaxf(mx0, __shfl_xor_sync(0xffffffffu, mx0, 1));
        mx0 = fmaxf(mx0, __shfl_xor_sync(0xffffffffu, mx0, 2));
        mx1 = fmaxf(mx1, __shfl_xor_sync(0xffffffffu, mx1, 1));
        mx1 = fmaxf(mx1, __shfl_xor_sync(0xffffffffu, mx1, 2));
        float al0 = __expf(m0 - mx0), al1 = __expf(m1 - mx1);
        m0 = mx0; m1 = mx1;
        float s0 = 0.0f, s1 = 0.0f;
        #pragma unroll
        for (int nt = 0; nt < 8; nt++) {
            sacc[nt][0] = __expf(sacc[nt][0] - m0);
            sacc[nt][1] = __expf(sacc[nt][1] - m0);
            sacc[nt][2] = __expf(sacc[nt][2] - m1);
            sacc[nt][3] = __expf(sacc[nt][3] - m1);
            s0 += sacc[nt][0] + sacc[nt][1];
            s1 += sacc[nt][2] + sacc[nt][3];
        }
        s0 += __shfl_xor_sync(0xffffffffu, s0, 1);
        s0 += __shfl_xor_sync(0xffffffffu, s0, 2);
        s1 += __shfl_xor_sync(0xffffffffu, s1, 1);
        s1 += __shfl_xor_sync(0xffffffffu, s1, 2);
        l0 = l0 * al0 + s0;
        l1 = l1 * al1 + s1;
        #pragma unroll
        for (int nt = 0; nt < 8; nt++) {
            oacc[nt][0] *= al0; oacc[nt][1] *= al0;
            oacc[nt][2] *= al1; oacc[nt][3] *= al1;
        }

        // ---- PV: O += Phi Vhi + Plo Vhi + Phi Vlo ----
        #pragma unroll
        for (int kk = 0; kk < 4; kk++) {
            uint32_t ah[4], al_[4];
            split_pair(sacc[2 * kk][0],     sacc[2 * kk][1],     ah[0], al_[0]);
            split_pair(sacc[2 * kk][2],     sacc[2 * kk][3],     ah[1], al_[1]);
            split_pair(sacc[2 * kk + 1][0], sacc[2 * kk + 1][1], ah[2], al_[2]);
            split_pair(sacc[2 * kk + 1][2], sacc[2 * kk + 1][3], ah[3], al_[3]);
            uint32_t key = kk * 16 + (g & 1) * 8 + r;
            #pragma unroll
            for (int nt2 = 0; nt2 < 4; nt2++) {
                uint32_t doff = (((nt2 * 2 + (g >> 1)) ^ r) << 4);
                uint32_t vb[4];
                ldm_x4_t(vb, Vhb + key * 128 + doff);
                mma_bf16(oacc[2 * nt2],     ah,  vb + 0);
                mma_bf16(oacc[2 * nt2 + 1], ah,  vb + 2);
                mma_bf16(oacc[2 * nt2],     al_, vb + 0);
                mma_bf16(oacc[2 * nt2 + 1], al_, vb + 2);
                uint32_t vc[4];
                ldm_x4_t(vc, Vlb + key * 128 + doff);
                mma_bf16(oacc[2 * nt2],     ah,  vc + 0);
                mma_bf16(oacc[2 * nt2 + 1], ah,  vc + 2);
            }
        }
        __syncthreads();
    }

    // ---- normalize + write ctx [b*s, h*64+d] ----
    const int b_ = bh / NH, h_ = bh % NH;
    const int row0 = q0 + warp * 16 + (lane >> 2);
    const int row1 = row0 + 8;
    const int col = (lane & 3) * 2;
    const float i0 = 1.0f / l0, i1 = 1.0f / l1;
    #pragma unroll
    for (int nt = 0; nt < 8; nt++) {
        int d = h_ * 64 + nt * 8 + col;
        float2 v0 = {oacc[nt][0] * i0, oacc[nt][1] * i0};
        float2 v1 = {oacc[nt][2] * i1, oacc[nt][3] * i1};
        *(float2*)&ctx[((size_t)b_ * SEQ + row0) * HID + d] = v0;
        *(float2*)&ctx[((size_t)b_ * SEQ + row1) * HID + d] = v1;
    }
}

// ---------------------------------------------------------------------------
extern "C" void kernel_launch(void* const* d_in, const int* in_sizes, int n_in,
                              void* d_out, int out_size)
{
    const float* query = (const float*)d_in[0];
    const float* key   = (const float*)d_in[1];
    const float* value = (const float*)d_in[2];
    const float* Wq = (const float*)d_in[3];
    const float* bq = (const float*)d_in[4];
    const float* Wk = (const float*)d_in[5];
    const float* bk = (const float*)d_in[6];
    const float* Wv = (const float*)d_in[7];
    const float* bv = (const float*)d_in[8];
    const float* Wo = (const float*)d_in[9];
    const float* bo = (const float*)d_in[10];
    float* out = (float*)d_out;

    __nv_bfloat16 *abuf, *bbuf, *qh, *ql, *kh, *kl, *vh, *vl;
    float *cbuf;
    cudaGetSymbolAddress((void**)&abuf, g_A);
    cudaGetSymbolAddress((void**)&bbuf, g_B);
    cudaGetSymbolAddress((void**)&qh, g_Qh);
    cudaGetSymbolAddress((void**)&ql, g_Ql);
    cudaGetSymbolAddress((void**)&kh, g_Kh);
    cudaGetSymbolAddress((void**)&kl, g_Kl);
    cudaGetSymbolAddress((void**)&vh, g_Vh);
    cudaGetSymbolAddress((void**)&vl, g_Vl);
    cudaGetSymbolAddress((void**)&cbuf, g_CTX);

    cudaFuncSetAttribute(gemm_mma_kernel,
                         cudaFuncAttributeMaxDynamicSharedMemorySize, SMEM_GEMM);
    cudaFuncSetAttribute(attn_mma_kernel,
                         cudaFuncAttributeMaxDynamicSharedMemorySize, SMEM_ATTN);

    const int splitA_blocks = MTOT * (HID / 2) / 256;
    const int splitB_blocks = HID * (HID / 2) / 256;
    dim3 ggrid(HID / GN, MTOT / GM);

    // Q projection (pre-scaled by 1/sqrt(64))
    split_kernel<<<splitA_blocks, 256>>>(query, abuf, MTOT, 0);
    split_kernel<<<splitB_blocks, 256>>>(Wq, bbuf, HID, 1);
    gemm_mma_kernel<<<ggrid, 256, SMEM_GEMM>>>(abuf, bbuf, bq, nullptr, qh, ql, 1, 0.125f);
    // K projection
    split_kernel<<<splitA_blocks, 256>>>(key, abuf, MTOT, 0);
    split_kernel<<<splitB_blocks, 256>>>(Wk, bbuf, HID, 1);
    gemm_mma_kernel<<<ggrid, 256, SMEM_GEMM>>>(abuf, bbuf, bk, nullptr, kh, kl, 1, 1.0f);
    // V projection
    split_kernel<<<splitA_blocks, 256>>>(value, abuf, MTOT, 0);
    split_kernel<<<splitB_blocks, 256>>>(Wv, bbuf, HID, 1);
    gemm_mma_kernel<<<ggrid, 256, SMEM_GEMM>>>(abuf, bbuf, bv, nullptr, vh, vl, 1, 1.0f);

    // attention (tensor cores)
    dim3 agrid(SEQ / 128, BATCH * NH);
    attn_mma_kernel<<<agrid, 256, SMEM_ATTN>>>(cbuf);

    // output projection
    split_kernel<<<splitA_blocks, 256>>>(cbuf, abuf, MTOT, 0);
    split_kernel<<<splitB_blocks, 256>>>(Wo, bbuf, HID, 1);
    gemm_mma_kernel<<<ggrid, 256, SMEM_GEMM>>>(abuf, bbuf, bo, out, nullptr, nullptr, 0, 1.0f);
}

// round 12
// speedup vs baseline: 3.9171x; 1.0159x over previous
#include <cuda_runtime.h>
#include <cuda_bf16.h>
#include <cstdint>
#include <math.h>

#define BATCH 2
#define SEQ   2048
#define HID   1024
#define NH    16
#define HD    64
#define MTOT  (BATCH*SEQ)
#define KS    (3*HID)

// static scratch (no runtime allocation allowed)
__device__ __align__(16) __nv_bfloat16 g_A0[(size_t)MTOT * KS];
__device__ __align__(16) __nv_bfloat16 g_A1[(size_t)MTOT * KS];
__device__ __align__(16) __nv_bfloat16 g_A2[(size_t)MTOT * KS];
__device__ __align__(16) __nv_bfloat16 g_B0[(size_t)HID * KS];
__device__ __align__(16) __nv_bfloat16 g_B1[(size_t)HID * KS];
__device__ __align__(16) __nv_bfloat16 g_B2[(size_t)HID * KS];
__device__ __align__(16) __nv_bfloat16 g_Qh[(size_t)BATCH*NH*SEQ*HD];
__device__ __align__(16) __nv_bfloat16 g_Ql[(size_t)BATCH*NH*SEQ*HD];
__device__ __align__(16) __nv_bfloat16 g_Kh[(size_t)BATCH*NH*SEQ*HD];
__device__ __align__(16) __nv_bfloat16 g_Kl[(size_t)BATCH*NH*SEQ*HD];
__device__ __align__(16) __nv_bfloat16 g_Vh[(size_t)BATCH*NH*SEQ*HD];
__device__ __align__(16) __nv_bfloat16 g_Vl[(size_t)BATCH*NH*SEQ*HD];

__device__ __forceinline__ uint32_t smem_u32(const void* p) {
    uint32_t a;
    asm("{ .reg .u64 t; cvta.to.shared.u64 t, %1; cvt.u32.u64 %0, t; }" : "=r"(a) : "l"(p));
    return a;
}
#define CP_ASYNC16(dst, src) \
    asm volatile("cp.async.cg.shared.global [%0], [%1], 16;" :: "r"(dst), "l"(src))
#define CP_COMMIT()  asm volatile("cp.async.commit_group;" ::: "memory")
#define CP_WAIT0()   asm volatile("cp.async.wait_group 0;" ::: "memory")
#define CP_WAIT1()   asm volatile("cp.async.wait_group 1;" ::: "memory")

__device__ __forceinline__ void ldm_x4(uint32_t* f, uint32_t addr) {
    asm volatile("ldmatrix.sync.aligned.m8n8.x4.shared.b16 {%0,%1,%2,%3}, [%4];"
        : "=r"(f[0]), "=r"(f[1]), "=r"(f[2]), "=r"(f[3]) : "r"(addr));
}
__device__ __forceinline__ void ldm_x4_t(uint32_t* f, uint32_t addr) {
    asm volatile("ldmatrix.sync.aligned.m8n8.x4.trans.shared.b16 {%0,%1,%2,%3}, [%4];"
        : "=r"(f[0]), "=r"(f[1]), "=r"(f[2]), "=r"(f[3]) : "r"(addr));
}
__device__ __forceinline__ void mma_bf16(float* d, const uint32_t* a, const uint32_t* b) {
    asm volatile("mma.sync.aligned.m16n8k16.row.col.f32.bf16.bf16.f32 "
        "{%0,%1,%2,%3}, {%4,%5,%6,%7}, {%8,%9}, {%0,%1,%2,%3};"
        : "+f"(d[0]), "+f"(d[1]), "+f"(d[2]), "+f"(d[3])
        : "r"(a[0]), "r"(a[1]), "r"(a[2]), "r"(a[3]), "r"(b[0]), "r"(b[1]));
}
__device__ __forceinline__ uint32_t pack_bf2(float lo, float hi) {
    uint32_t r;
    asm("cvt.rn.bf16x2.f32 %0, %1, %2;" : "=r"(r) : "f"(hi), "f"(lo));
    return r;
}
__device__ __forceinline__ void split_pair(float a, float b, uint32_t& hi, uint32_t& lo) {
    __nv_bfloat16 ha = __float2bfloat16(a), hb = __float2bfloat16(b);
    hi = (uint32_t)__bfloat16_as_ushort(ha) | ((uint32_t)__bfloat16_as_ushort(hb) << 16);
    lo = pack_bf2(a - __bfloat162float(ha), b - __bfloat162float(hb));
}

// Split: fp32 [nrows,1024] -> bf16 [nrows,3072], up to 3 tensors per grid
// bmode=0 (A-style): [hi | hi | lo];  bmode=1 (B-style): [hi | lo | hi]
__global__ __launch_bounds__(256) void split3_kernel(
    const float* __restrict__ X0, const float* __restrict__ X1, const float* __restrict__ X2,
    __nv_bfloat16* __restrict__ O0, __nv_bfloat16* __restrict__ O1, __nv_bfloat16* __restrict__ O2,
    int nrows, int bmode)
{
    int idx = blockIdx.x * 256 + threadIdx.x;
    int per = nrows * (HID / 2);
    if (idx >= 3 * per) return;
    int which = idx / per;
    idx -= which * per;
    const float* X = (which == 0) ? X0 : (which == 1) ? X1 : X2;
    __nv_bfloat16* out = (which == 0) ? O0 : (which == 1) ? O1 : O2;

    int row = idx >> 9;
    int c2 = (idx & 511) * 2;
    float2 x = *(const float2*)(X + (size_t)row * HID + c2);
    __nv_bfloat16 h0 = __float2bfloat16(x.x), h1 = __float2bfloat16(x.y);
    __nv_bfloat162 hi, lo;
    hi.x = h0; hi.y = h1;
    lo.x = __float2bfloat16(x.x - __bfloat162float(h0));
    lo.y = __float2bfloat16(x.y - __bfloat162float(h1));
    __nv_bfloat162* o = (__nv_bfloat162*)(out + (size_t)row * KS + c2);
    o[0] = hi;
    if (bmode == 0) { o[512] = hi; o[1024] = lo; }
    else            { o[512] = lo; o[1024] = hi; }
}

// Warp-MMA bf16 GEMM, 3-stage cp.async pipeline, grid.z batches
#define GM 128
#define GN 128
#define GK 64
#define NKC (KS / GK)
#define SMEM_GEMM (6 * 16384)

struct GemmArgs {
    const __nv_bfloat16* A[3];
    const __nv_bfloat16* B[3];
    const float* bias[3];
    __nv_bfloat16* oh[3];
    __nv_bfloat16* ol[3];
    float scale[3];
    float* out;
    int mode;
};

__global__ __launch_bounds__(256, 2) void gemm_mma_kernel(GemmArgs ga)
{
    extern __shared__ char smem[];
    const uint32_t sb = smem_u32(smem);
    const int z = blockIdx.z;
    const __nv_bfloat16* A = ga.A[z];
    const __nv_bfloat16* B = ga.B[z];
    const float* bias = ga.bias[z];

    const int tid  = threadIdx.x;
    const int wid  = tid >> 5;
    const int lane = tid & 31;
    const int warp_m = wid & 1;
    const int warp_n = wid >> 1;
    const int m0 = blockIdx.y * GM;
    const int n0 = blockIdx.x * GN;

    const uint32_t TA[3] = {sb, sb + 32768, sb + 65536};
    const uint32_t TB[3] = {sb + 16384, sb + 49152, sb + 81920};

    const char* Abase = (const char*)(A + (size_t)m0 * KS);
    const char* Bbase = (const char*)(B + (size_t)n0 * KS);

    auto load_chunk = [&](int st, int kc) {
        const char* Ap = Abase + (size_t)kc * (GK * 2);
        const char* Bp = Bbase + (size_t)kc * (GK * 2);
        #pragma unroll
        for (int i = 0; i < 4; i++) {
            int cid = tid + i * 256;
            int row = cid >> 3, c16 = cid & 7;
            uint32_t off = row * 128 + c16 * 16;
            off ^= ((off >> 3) & 0x70);
            CP_ASYNC16(TA[st] + off, Ap + (size_t)row * (KS * 2) + c16 * 16);
            CP_ASYNC16(TB[st] + off, Bp + (size_t)row * (KS * 2) + c16 * 16);
        }
        CP_COMMIT();
    };

    const int g = lane >> 3, r = lane & 7;
    const uint32_t a_row = warp_m * 64 + (g & 1) * 8 + r;
    const int a_kg = g >> 1;
    const uint32_t b_row = warp_n * 32 + (g >> 1) * 8 + r;
    const int b_kg = g & 1;

    float acc[4][4][4] = {};

    load_chunk(0, 0);
    load_chunk(1, 1);

    int st = 0;
    for (int kc = 0; kc < NKC; kc++) {
        if (kc + 1 < NKC) CP_WAIT1(); else CP_WAIT0();
        __syncthreads();
        if (kc + 2 < NKC) {
            int nst = st + 2; if (nst >= 3) nst -= 3;
            load_chunk(nst, kc + 2);
        }

        const uint32_t Asm = TA[st] + a_row * 128;
        const uint32_t Bsm = TB[st] + b_row * 128;

        #pragma unroll
        for (int ks = 0; ks < 4; ks++) {
            uint32_t af[4][4];
            #pragma unroll
            for (int mt = 0; mt < 4; mt++)
                ldm_x4(af[mt], Asm + mt * 2048 + (((ks * 2 + a_kg) ^ r) << 4));
            uint32_t bf[4][2];
            #pragma unroll
            for (int nt2 = 0; nt2 < 2; nt2++) {
                uint32_t t[4];
                ldm_x4(t, Bsm + nt2 * 2048 + (((ks * 2 + b_kg) ^ r) << 4));
                bf[nt2 * 2 + 0][0] = t[0]; bf[nt2 * 2 + 0][1] = t[1];
                bf[nt2 * 2 + 1][0] = t[2]; bf[nt2 * 2 + 1][1] = t[3];
            }
            #pragma unroll
            for (int mt = 0; mt < 4; mt++)
                #pragma unroll
                for (int nt = 0; nt < 4; nt++)
                    mma_bf16(acc[mt][nt], af[mt], bf[nt]);
        }
        if (++st >= 3) st -= 3;
    }

    const int mrow = m0 + warp_m * 64 + (lane >> 2);
    const int ncol = n0 + warp_n * 32 + (lane & 3) * 2;
    const float scale = ga.scale[z];
    #pragma unroll
    for (int mt = 0; mt < 4; mt++) {
        #pragma unroll
        for (int nt = 0; nt < 4; nt++) {
            int n = ncol + nt * 8;
            float b0 = __ldg(bias + n), b1 = __ldg(bias + n + 1);
            #pragma unroll
            for (int half = 0; half < 2; half++) {
                int m = mrow + mt * 16 + half * 8;
                float v0 = acc[mt][nt][half * 2 + 0] + b0;
                float v1 = acc[mt][nt][half * 2 + 1] + b1;
                if (ga.mode == 1) {
                    v0 *= scale; v1 *= scale;
                    int b = m / SEQ, s = m % SEQ;
                    int h = n >> 6, d0 = n & 63;
                    size_t idx = (((size_t)b * NH + h) * SEQ + s) * HD + d0;
                    __nv_bfloat16 h0 = __float2bfloat16(v0), h1 = __float2bfloat16(v1);
                    __nv_bfloat162 hi2, lo2;
                    hi2.x = h0; hi2.y = h1;
                    lo2.x = __float2bfloat16(v0 - __bfloat162float(h0));
                    lo2.y = __float2bfloat16(v1 - __bfloat162float(h1));
                    *(__nv_bfloat162*)(ga.oh[z] + idx) = hi2;
                    *(__nv_bfloat162*)(ga.ol[z] + idx) = lo2;
                } else {
                    float* dst = ga.out + (size_t)m * HID + n;
                    dst[0] = v0; dst[1] = v1;
                }
            }
        }
    }
}

// Tensor-core flash attention; epilogue writes 3-segment A'' for output GEMM
#define SMEM_ATTN 65536

__global__ __launch_bounds__(256) void attn_mma_kernel(__nv_bfloat16* __restrict__ actx)
{
    extern __shared__ char smem[];
    const uint32_t sb = smem_u32(smem);
    const int tid = threadIdx.x, warp = tid >> 5, lane = tid & 31;
    const int g = lane >> 3, r = lane & 7;
    const int bh = blockIdx.y;
    const int q0 = blockIdx.x * 128;

    const char* Qh = (const char*)(g_Qh + (size_t)bh * SEQ * HD);
    const char* Ql = (const char*)(g_Ql + (size_t)bh * SEQ * HD);
    const char* Kh = (const char*)(g_Kh + (size_t)bh * SEQ * HD);
    const char* Kl = (const char*)(g_Kl + (size_t)bh * SEQ * HD);
    const char* Vh = (const char*)(g_Vh + (size_t)bh * SEQ * HD);
    const char* Vl = (const char*)(g_Vl + (size_t)bh * SEQ * HD);

    {
        const char* srcs[2] = {Qh, Ql};
        #pragma unroll
        for (int i = 0; i < 8; i++) {
            int cid = tid + i * 256;
            int arr = cid >> 10;
            int rem = cid & 1023;
            int row = rem >> 3, ch = rem & 7;
            uint32_t off = row * 128 + ((ch ^ (row & 7)) << 4);
            CP_ASYNC16(sb + arr * 16384 + off,
                       srcs[arr] + (size_t)(q0 + row) * 128 + ch * 16);
        }
        CP_COMMIT(); CP_WAIT0();
        __syncthreads();
    }
    uint32_t qf[2][4][4];
    #pragma unroll
    for (int seg = 0; seg < 2; seg++) {
        uint32_t base = sb + seg * 16384;
        #pragma unroll
        for (int ks = 0; ks < 4; ks++) {
            uint32_t row = warp * 16 + (g & 1) * 8 + r;
            ldm_x4(qf[seg][ks], base + row * 128 + (((ks * 2 + (g >> 1)) ^ r) << 4));
        }
    }
    __syncthreads();

    auto kvload = [&](int st, int kt) {
        uint32_t stb = sb + st * 32768;
        const char* srcs[4] = {Kh, Kl, Vh, Vl};
        #pragma unroll
        for (int i = 0; i < 8; i++) {
            int cid = tid + i * 256;
            int arr = cid >> 9;
            int rem = cid & 511;
            int row = rem >> 3, ch = rem & 7;
            uint32_t off = row * 128 + ((ch ^ (row & 7)) << 4);
            CP_ASYNC16(stb + arr * 8192 + off,
                       srcs[arr] + (size_t)(kt * 64 + row) * 128 + ch * 16);
        }
        CP_COMMIT();
    };

    float oacc[8][4] = {};
    float m0 = -1e30f, m1 = -1e30f, l0 = 0.0f, l1 = 0.0f;

    kvload(0, 0);

    for (int kt = 0; kt < SEQ / 64; kt++) {
        int cur = kt & 1;
        if (kt + 1 < SEQ / 64) { kvload(1 - cur, kt + 1); CP_WAIT1(); }
        else                   { CP_WAIT0(); }
        __syncthreads();

        const uint32_t Khb = sb + cur * 32768;
        const uint32_t Klb = Khb + 8192;
        const uint32_t Vhb = Khb + 16384;
        const uint32_t Vlb = Khb + 24576;

        float sacc[8][4] = {};
        #pragma unroll
        for (int ks = 0; ks < 4; ks++) {
            #pragma unroll
            for (int nt2 = 0; nt2 < 4; nt2++) {
                uint32_t brow = nt2 * 16 + (g >> 1) * 8 + r;
                uint32_t koff = ((ks * 2 + (g & 1)) ^ r) << 4;
                uint32_t t[4];
                ldm_x4(t, Khb + brow * 128 + koff);
                mma_bf16(sacc[2 * nt2],     qf[0][ks], t + 0);
                mma_bf16(sacc[2 * nt2 + 1], qf[0][ks], t + 2);
                mma_bf16(sacc[2 * nt2],     qf[1][ks], t + 0);
                mma_bf16(sacc[2 * nt2 + 1], qf[1][ks], t + 2);
                uint32_t u[4];
                ldm_x4(u, Klb + brow * 128 + koff);
                mma_bf16(sacc[2 * nt2],     qf[0][ks], u + 0);
                mma_bf16(sacc[2 * nt2 + 1], qf[0][ks], u + 2);
            }
        }

        float mx0 = m0, mx1 = m1;
        #pragma unroll
        for (int nt = 0; nt < 8; nt++) {
            mx0 = fmaxf(mx0, fmaxf(sacc[nt][0], sacc[nt][1]));
            mx1 = fmaxf(mx1, fmaxf(sacc[nt][2], sacc[nt][3]));
        }
        mx0 = fmaxf(mx0, __shfl_xor_sync(0xffffffffu, mx0, 1));
        mx0 = fmaxf(mx0, __shfl_xor_sync(0xffffffffu, mx0, 2));
        mx1 = fmaxf(mx1, __shfl_xor_sync(0xffffffffu, mx1, 1));
        mx1 = fmaxf(mx1, __shfl_xor_sync(0xffffffffu, mx1, 2));
        float al0 = __expf(m0 - mx0), al1 = __expf(m1 - mx1);
        m0 = mx0; m1 = mx1;
        float s0 = 0.0f, s1 = 0.0f;
        #pragma unroll
        for (int nt = 0; nt < 8; nt++) {
            sacc[nt][0] = __expf(sacc[nt][0] - m0);
            sacc[nt][1] = __expf(sacc[nt][1] - m0);
            sacc[nt][2] = __expf(sacc[nt][2] - m1);
            sacc[nt][3] = __expf(sacc[nt][3] - m1);
            s0 += sacc[nt][0] + sacc[nt][1];
            s1 += sacc[nt][2] + sacc[nt][3];
        }
        s0 += __shfl_xor_sync(0xffffffffu, s0, 1);
        s0 += __shfl_xor_sync(0xffffffffu, s0, 2);
        s1 += __shfl_xor_sync(0xffffffffu, s1, 1);
        s1 += __shfl_xor_sync(0xffffffffu, s1, 2);
        l0 = l0 * al0 + s0;
        l1 = l1 * al1 + s1;
        #pragma unroll
        for (int nt = 0; nt < 8; nt++) {
            oacc[nt][0] *= al0; oacc[nt][1] *= al0;
            oacc[nt][2] *= al1; oacc[nt][3] *= al1;
        }

        #pragma unroll
        for (int kk = 0; kk < 4; kk++) {
            uint32_t ah[4], al_[4];
            split_pair(sacc[2 * kk][0],     sacc[2 * kk][1],     ah[0], al_[0]);
            split_pair(sacc[2 * kk][2],     sacc[2 * kk][3],     ah[1], al_[1]);
            split_pair(sacc[2 * kk + 1][0], sacc[2 * kk + 1][1], ah[2], al_[2]);
            split_pair(sacc[2 * kk + 1][2], sacc[2 * kk + 1][3], ah[3], al_[3]);
            uint32_t key = kk * 16 + (g & 1) * 8 + r;
            #pragma unroll
            for (int nt2 = 0; nt2 < 4; nt2++) {
                uint32_t doff = (((nt2 * 2 + (g >> 1)) ^ r) << 4);
                uint32_t vb[4];
                ldm_x4_t(vb, Vhb + key * 128 + doff);
                mma_bf16(oacc[2 * nt2],     ah,  vb + 0);
                mma_bf16(oacc[2 * nt2 + 1], ah,  vb + 2);
                mma_bf16(oacc[2 * nt2],     al_, vb + 0);
                mma_bf16(oacc[2 * nt2 + 1], al_, vb + 2);
                uint32_t vc[4];
                ldm_x4_t(vc, Vlb + key * 128 + doff);
                mma_bf16(oacc[2 * nt2],     ah,  vc + 0);
                mma_bf16(oacc[2 * nt2 + 1], ah,  vc + 2);
            }
        }
        __syncthreads();
    }

    const int b_ = bh / NH, h_ = bh % NH;
    const int row0 = q0 + warp * 16 + (lane >> 2);
    const int col = (lane & 3) * 2;
    const float i0 = 1.0f / l0, i1 = 1.0f / l1;
    #pragma unroll
    for (int half = 0; half < 2; half++) {
        int srow = row0 + half * 8;
        __nv_bfloat16* arow = actx + (size_t)(b_ * SEQ + srow) * KS;
        float inv = half ? i1 : i0;
        #pragma unroll
        for (int nt = 0; nt < 8; nt++) {
            int d = h_ * 64 + nt * 8 + col;
            float v0 = oacc[nt][half * 2 + 0] * inv;
            float v1 = oacc[nt][half * 2 + 1] * inv;
            __nv_bfloat16 h0 = __float2bfloat16(v0), h1 = __float2bfloat16(v1);
            __nv_bfloat162 hi2, lo2;
            hi2.x = h0; hi2.y = h1;
            lo2.x = __float2bfloat16(v0 - __bfloat162float(h0));
            lo2.y = __float2bfloat16(v1 - __bfloat162float(h1));
            *(__nv_bfloat162*)(arow + d) = hi2;
            *(__nv_bfloat162*)(arow + 1024 + d) = hi2;
            *(__nv_bfloat162*)(arow + 2048 + d) = lo2;
        }
    }
}

extern "C" void kernel_launch(void* const* d_in, const int* in_sizes, int n_in,
                              void* d_out, int out_size)
{
    const float* query = (const float*)d_in[0];
    const float* key   = (const float*)d_in[1];
    const float* value = (const float*)d_in[2];
    const float* Wq = (const float*)d_in[3];
    const float* bq = (const float*)d_in[4];
    const float* Wk = (const float*)d_in[5];
    const float* bk = (const float*)d_in[6];
    const float* Wv = (const float*)d_in[7];
    const float* bv = (const float*)d_in[8];
    const float* Wo = (const float*)d_in[9];
    const float* bo = (const float*)d_in[10];
    float* out = (float*)d_out;

    __nv_bfloat16 *a0, *a1, *a2, *b0, *b1, *b2, *qh, *ql, *kh, *kl, *vh, *vl;
    cudaGetSymbolAddress((void**)&a0, g_A0);
    cudaGetSymbolAddress((void**)&a1, g_A1);
    cudaGetSymbolAddress((void**)&a2, g_A2);
    cudaGetSymbolAddress((void**)&b0, g_B0);
    cudaGetSymbolAddress((void**)&b1, g_B1);
    cudaGetSymbolAddress((void**)&b2, g_B2);
    cudaGetSymbolAddress((void**)&qh, g_Qh);
    cudaGetSymbolAddress((void**)&ql, g_Ql);
    cudaGetSymbolAddress((void**)&kh, g_Kh);
    cudaGetSymbolAddress((void**)&kl, g_Kl);
    cudaGetSymbolAddress((void**)&vh, g_Vh);
    cudaGetSymbolAddress((void**)&vl, g_Vl);

    cudaFuncSetAttribute(gemm_mma_kernel,
                         cudaFuncAttributeMaxDynamicSharedMemorySize, SMEM_GEMM);
    cudaFuncSetAttribute(attn_mma_kernel,
                         cudaFuncAttributeMaxDynamicSharedMemorySize, SMEM_ATTN);

    int blkA3 = (3 * MTOT * (HID / 2) + 255) / 256;
    int blkB3 = (3 * HID * (HID / 2) + 255) / 256;
    int blkB1 = (HID * (HID / 2) + 255) / 256;
    split3_kernel<<<blkA3, 256>>>(query, key, value, a0, a1, a2, MTOT, 0);
    split3_kernel<<<blkB3, 256>>>(Wq, Wk, Wv, b0, b1, b2, HID, 1);

    GemmArgs pa = {};
    pa.A[0] = a0; pa.A[1] = a1; pa.A[2] = a2;
    pa.B[0] = b0; pa.B[1] = b1; pa.B[2] = b2;
    pa.bias[0] = bq; pa.bias[1] = bk; pa.bias[2] = bv;
    pa.oh[0] = qh; pa.oh[1] = kh; pa.oh[2] = vh;
    pa.ol[0] = ql; pa.ol[1] = kl; pa.ol[2] = vl;
    pa.scale[0] = 0.125f; pa.scale[1] = 1.0f; pa.scale[2] = 1.0f;
    pa.out = nullptr; pa.mode = 1;
    gemm_mma_kernel<<<dim3(HID / GN, MTOT / GM, 3), 256, SMEM_GEMM>>>(pa);

    // Wo split into b1 (only `per` blocks launched, so which==0 for all threads)
    split3_kernel<<<blkB1, 256>>>(Wo, Wo, Wo, b1, b1, b1, HID, 1);

    attn_mma_kernel<<<dim3(SEQ / 128, BATCH * NH), 256, SMEM_ATTN>>>(a0);

    GemmArgs oa = {};
    oa.A[0] = a0; oa.B[0] = b1; oa.bias[0] = bo;
    oa.scale[0] = 1.0f; oa.out = out; oa.mode = 0;
    gemm_mma_kernel<<<dim3(HID / GN, MTOT / GM, 1), 256, SMEM_GEMM>>>(oa);
}

// round 16
// speedup vs baseline: 3.9401x; 1.0059x over previous
#include <cuda_runtime.h>
#include <cuda_bf16.h>
#include <cstdint>
#include <math.h>

#define BATCH 2
#define SEQ   2048
#define HID   1024
#define NH    16
#define HD    64
#define MTOT  (BATCH*SEQ)
#define KS2   (2*HID)   // [hi | lo]

// static scratch (no runtime allocation allowed)
__device__ __align__(16) __nv_bfloat16 g_A0[(size_t)MTOT * KS2];
__device__ __align__(16) __nv_bfloat16 g_A1[(size_t)MTOT * KS2];
__device__ __align__(16) __nv_bfloat16 g_A2[(size_t)MTOT * KS2];
__device__ __align__(16) __nv_bfloat16 g_B0[(size_t)HID * KS2];
__device__ __align__(16) __nv_bfloat16 g_B1[(size_t)HID * KS2];
__device__ __align__(16) __nv_bfloat16 g_B2[(size_t)HID * KS2];
__device__ __align__(16) __nv_bfloat16 g_Qh[(size_t)BATCH*NH*SEQ*HD];
__device__ __align__(16) __nv_bfloat16 g_Ql[(size_t)BATCH*NH*SEQ*HD];
__device__ __align__(16) __nv_bfloat16 g_Kh[(size_t)BATCH*NH*SEQ*HD];
__device__ __align__(16) __nv_bfloat16 g_Kl[(size_t)BATCH*NH*SEQ*HD];
__device__ __align__(16) __nv_bfloat16 g_Vh[(size_t)BATCH*NH*SEQ*HD];
__device__ __align__(16) __nv_bfloat16 g_Vl[(size_t)BATCH*NH*SEQ*HD];

__device__ __forceinline__ uint32_t smem_u32(const void* p) {
    uint32_t a;
    asm("{ .reg .u64 t; cvta.to.shared.u64 t, %1; cvt.u32.u64 %0, t; }" : "=r"(a) : "l"(p));
    return a;
}
#define CP_ASYNC16(dst, src) \
    asm volatile("cp.async.cg.shared.global [%0], [%1], 16;" :: "r"(dst), "l"(src))
#define CP_COMMIT()  asm volatile("cp.async.commit_group;" ::: "memory")
#define CP_WAIT0()   asm volatile("cp.async.wait_group 0;" ::: "memory")
#define CP_WAIT1()   asm volatile("cp.async.wait_group 1;" ::: "memory")

__device__ __forceinline__ void ldm_x4(uint32_t* f, uint32_t addr) {
    asm volatile("ldmatrix.sync.aligned.m8n8.x4.shared.b16 {%0,%1,%2,%3}, [%4];"
        : "=r"(f[0]), "=r"(f[1]), "=r"(f[2]), "=r"(f[3]) : "r"(addr));
}
__device__ __forceinline__ void ldm_x4_t(uint32_t* f, uint32_t addr) {
    asm volatile("ldmatrix.sync.aligned.m8n8.x4.trans.shared.b16 {%0,%1,%2,%3}, [%4];"
        : "=r"(f[0]), "=r"(f[1]), "=r"(f[2]), "=r"(f[3]) : "r"(addr));
}
__device__ __forceinline__ void mma_bf16(float* d, const uint32_t* a, const uint32_t* b) {
    asm volatile("mma.sync.aligned.m16n8k16.row.col.f32.bf16.bf16.f32 "
        "{%0,%1,%2,%3}, {%4,%5,%6,%7}, {%8,%9}, {%0,%1,%2,%3};"
        : "+f"(d[0]), "+f"(d[1]), "+f"(d[2]), "+f"(d[3])
        : "r"(a[0]), "r"(a[1]), "r"(a[2]), "r"(a[3]), "r"(b[0]), "r"(b[1]));
}
__device__ __forceinline__ uint32_t pack_bf2(float lo, float hi) {
    uint32_t r;
    asm("cvt.rn.bf16x2.f32 %0, %1, %2;" : "=r"(r) : "f"(hi), "f"(lo));
    return r;
}
__device__ __forceinline__ void split_pair(float a, float b, uint32_t& hi, uint32_t& lo) {
    __nv_bfloat16 ha = __float2bfloat16(a), hb = __float2bfloat16(b);
    hi = (uint32_t)__bfloat16_as_ushort(ha) | ((uint32_t)__bfloat16_as_ushort(hb) << 16);
    lo = pack_bf2(a - __bfloat162float(ha), b - __bfloat162float(hb));
}

// Split: fp32 [nrows,1024] -> bf16 [nrows,2048] = [hi | lo]; up to 3 tensors
__global__ __launch_bounds__(256) void split3_kernel(
    const float* __restrict__ X0, const float* __restrict__ X1, const float* __restrict__ X2,
    __nv_bfloat16* __restrict__ O0, __nv_bfloat16* __restrict__ O1, __nv_bfloat16* __restrict__ O2,
    int nrows)
{
    int idx = blockIdx.x * 256 + threadIdx.x;
    int per = nrows * (HID / 2);
    if (idx >= 3 * per) return;
    int which = idx / per;
    idx -= which * per;
    const float* X = (which == 0) ? X0 : (which == 1) ? X1 : X2;
    __nv_bfloat16* out = (which == 0) ? O0 : (which == 1) ? O1 : O2;

    int row = idx >> 9;
    int c2 = (idx & 511) * 2;
    float2 x = *(const float2*)(X + (size_t)row * HID + c2);
    __nv_bfloat16 h0 = __float2bfloat16(x.x), h1 = __float2bfloat16(x.y);
    __nv_bfloat162 hi, lo;
    hi.x = h0; hi.y = h1;
    lo.x = __float2bfloat16(x.x - __bfloat162float(h0));
    lo.y = __float2bfloat16(x.y - __bfloat162float(h1));
    __nv_bfloat162* o = (__nv_bfloat162*)(out + (size_t)row * KS2 + c2);
    o[0] = hi;
    o[512] = lo;
}

// Warp-MMA bf16 GEMM over [hi|lo] operands: C = Ahi.Bhi + Ahi.Blo + Alo.Bhi
// Block 128x128, 4 warps (warp tile 64x64), superchunk BK=32 packs hi|lo in
// one 128B smem row. 3-stage cp.async pipeline. grid.z batches.
#define GM 128
#define GN 128
#define NKC2 32                   // 1024 / 32
#define SMEM_GEMM (3 * 32768)     // 3 stages x (A 16KB + B 16KB)

struct GemmArgs {
    const __nv_bfloat16* A[3];
    const __nv_bfloat16* B[3];
    const float* bias[3];
    __nv_bfloat16* oh[3];
    __nv_bfloat16* ol[3];
    float scale[3];
    float* out;
    int mode;
};

__global__ __launch_bounds__(128) void gemm_mma_kernel(GemmArgs ga)
{
    extern __shared__ char smem[];
    const uint32_t sb = smem_u32(smem);
    const int z = blockIdx.z;
    const __nv_bfloat16* A = ga.A[z];
    const __nv_bfloat16* B = ga.B[z];
    const float* bias = ga.bias[z];

    const int tid  = threadIdx.x;
    const int wid  = tid >> 5;
    const int lane = tid & 31;
    const int warp_m = wid & 1;        // 2 x 64 rows
    const int warp_n = wid >> 1;       // 2 x 64 cols
    const int m0 = blockIdx.y * GM;
    const int n0 = blockIdx.x * GN;

    const uint32_t TA[3] = {sb, sb + 32768, sb + 65536};
    const uint32_t TB[3] = {sb + 16384, sb + 49152, sb + 81920};

    const char* Abase = (const char*)(A + (size_t)m0 * KS2);
    const char* Bbase = (const char*)(B + (size_t)n0 * KS2);

    // superchunk kc: 128 rows x [hi 64B (ch 0-3) | lo 64B (ch 4-7)]
    auto load_chunk = [&](int st, int kc) {
        #pragma unroll
        for (int i = 0; i < 8; i++) {
            int cid = tid + i * 128;              // 0..1023
            int row = cid >> 3, c = cid & 7;
            uint32_t off = row * 128 + (((uint32_t)c ^ (row & 7)) << 4);
            size_t gsrc = (size_t)row * (KS2 * 2) + (size_t)kc * 64
                        + (c & 3) * 16 + ((c >> 2) ? 2048 : 0);
            CP_ASYNC16(TA[st] + off, Abase + gsrc);
            CP_ASYNC16(TB[st] + off, Bbase + gsrc);
        }
        CP_COMMIT();
    };

    const int g = lane >> 3, r = lane & 7;

    float acc[4][8][4] = {};   // [mt][nt][reg]

    load_chunk(0, 0);
    load_chunk(1, 1);

    int st = 0;
    for (int kc = 0; kc < NKC2; kc++) {
        if (kc + 1 < NKC2) CP_WAIT1(); else CP_WAIT0();
        __syncthreads();
        if (kc + 2 < NKC2) {
            int nst = st + 2; if (nst >= 3) nst -= 3;
            load_chunk(nst, kc + 2);
        }

        const uint32_t Ast = TA[st];
        const uint32_t Bst = TB[st];

        #pragma unroll
        for (int ks = 0; ks < 2; ks++) {
            uint32_t ah[4][4], alo[4][4];
            #pragma unroll
            for (int mt = 0; mt < 4; mt++) {
                uint32_t rowa = warp_m * 64 + mt * 16 + (g & 1) * 8 + r;
                uint32_t ch = ks * 2 + (g >> 1);
                ldm_x4(ah[mt],  Ast + rowa * 128 + ((ch ^ r) << 4));
                ldm_x4(alo[mt], Ast + rowa * 128 + (((ch + 4) ^ r) << 4));
            }
            #pragma unroll
            for (int nt2 = 0; nt2 < 4; nt2++) {
                uint32_t rowb = warp_n * 64 + nt2 * 16 + (g >> 1) * 8 + r;
                uint32_t ch = ks * 2 + (g & 1);
                uint32_t bh[4], bl[4];
                ldm_x4(bh, Bst + rowb * 128 + ((ch ^ r) << 4));
                ldm_x4(bl, Bst + rowb * 128 + (((ch + 4) ^ r) << 4));
                #pragma unroll
                for (int mt = 0; mt < 4; mt++) {
                    mma_bf16(acc[mt][2 * nt2],     ah[mt],  bh + 0);
                    mma_bf16(acc[mt][2 * nt2 + 1], ah[mt],  bh + 2);
                    mma_bf16(acc[mt][2 * nt2],     ah[mt],  bl + 0);
                    mma_bf16(acc[mt][2 * nt2 + 1], ah[mt],  bl + 2);
                    mma_bf16(acc[mt][2 * nt2],     alo[mt], bh + 0);
                    mma_bf16(acc[mt][2 * nt2 + 1], alo[mt], bh + 2);
                }
            }
        }
        if (++st >= 3) st -= 3;
    }

    const int mrow = m0 + warp_m * 64 + (lane >> 2);
    const int ncol = n0 + warp_n * 64 + (lane & 3) * 2;
    const float scale = ga.scale[z];
    #pragma unroll
    for (int mt = 0; mt < 4; mt++) {
        #pragma unroll
        for (int nt = 0; nt < 8; nt++) {
            int n = ncol + nt * 8;
            float b0 = __ldg(bias + n), b1 = __ldg(bias + n + 1);
            #pragma unroll
            for (int half = 0; half < 2; half++) {
                int m = mrow + mt * 16 + half * 8;
                float v0 = acc[mt][nt][half * 2 + 0] + b0;
                float v1 = acc[mt][nt][half * 2 + 1] + b1;
                if (ga.mode == 1) {
                    v0 *= scale; v1 *= scale;
                    int b = m / SEQ, s = m % SEQ;
                    int h = n >> 6, d0 = n & 63;
                    size_t idx = (((size_t)b * NH + h) * SEQ + s) * HD + d0;
                    __nv_bfloat16 h0 = __float2bfloat16(v0), h1 = __float2bfloat16(v1);
                    __nv_bfloat162 hi2, lo2;
                    hi2.x = h0; hi2.y = h1;
                    lo2.x = __float2bfloat16(v0 - __bfloat162float(h0));
                    lo2.y = __float2bfloat16(v1 - __bfloat162float(h1));
                    *(__nv_bfloat162*)(ga.oh[z] + idx) = hi2;
                    *(__nv_bfloat162*)(ga.ol[z] + idx) = lo2;
                } else {
                    float* dst = ga.out + (size_t)m * HID + n;
                    dst[0] = v0; dst[1] = v1;
                }
            }
        }
    }
}

// Tensor-core flash attention; epilogue writes 2-segment [hi|lo] A for out GEMM
#define SMEM_ATTN 65536

__global__ __launch_bounds__(256) void attn_mma_kernel(__nv_bfloat16* __restrict__ actx)
{
    extern __shared__ char smem[];
    const uint32_t sb = smem_u32(smem);
    const int tid = threadIdx.x, warp = tid >> 5, lane = tid & 31;
    const int g = lane >> 3, r = lane & 7;
    const int bh = blockIdx.y;
    const int q0 = blockIdx.x * 128;

    const char* Qh = (const char*)(g_Qh + (size_t)bh * SEQ * HD);
    const char* Ql = (const char*)(g_Ql + (size_t)bh * SEQ * HD);
    const char* Kh = (const char*)(g_Kh + (size_t)bh * SEQ * HD);
    const char* Kl = (const char*)(g_Kl + (size_t)bh * SEQ * HD);
    const char* Vh = (const char*)(g_Vh + (size_t)bh * SEQ * HD);
    const char* Vl = (const char*)(g_Vl + (size_t)bh * SEQ * HD);

    {
        const char* srcs[2] = {Qh, Ql};
        #pragma unroll
        for (int i = 0; i < 8; i++) {
            int cid = tid + i * 256;
            int arr = cid >> 10;
            int rem = cid & 1023;
            int row = rem >> 3, ch = rem & 7;
            uint32_t off = row * 128 + ((ch ^ (row & 7)) << 4);
            CP_ASYNC16(sb + arr * 16384 + off,
                       srcs[arr] + (size_t)(q0 + row) * 128 + ch * 16);
        }
        CP_COMMIT(); CP_WAIT0();
        __syncthreads();
    }
    uint32_t qf[2][4][4];
    #pragma unroll
    for (int seg = 0; seg < 2; seg++) {
        uint32_t base = sb + seg * 16384;
        #pragma unroll
        for (int ks = 0; ks < 4; ks++) {
            uint32_t row = warp * 16 + (g & 1) * 8 + r;
            ldm_x4(qf[seg][ks], base + row * 128 + (((ks * 2 + (g >> 1)) ^ r) << 4));
        }
    }
    __syncthreads();

    auto kvload = [&](int st, int kt) {
        uint32_t stb = sb + st * 32768;
        const char* srcs[4] = {Kh, Kl, Vh, Vl};
        #pragma unroll
        for (int i = 0; i < 8; i++) {
            int cid = tid + i * 256;
            int arr = cid >> 9;
            int rem = cid & 511;
            int row = rem >> 3, ch = rem & 7;
            uint32_t off = row * 128 + ((ch ^ (row & 7)) << 4);
            CP_ASYNC16(stb + arr * 8192 + off,
                       srcs[arr] + (size_t)(kt * 64 + row) * 128 + ch * 16);
        }
        CP_COMMIT();
    };

    float oacc[8][4] = {};
    float m0 = -1e30f, m1 = -1e30f, l0 = 0.0f, l1 = 0.0f;

    kvload(0, 0);

    for (int kt = 0; kt < SEQ / 64; kt++) {
        int cur = kt & 1;
        if (kt + 1 < SEQ / 64) { kvload(1 - cur, kt + 1); CP_WAIT1(); }
        else                   { CP_WAIT0(); }
        __syncthreads();

        const uint32_t Khb = sb + cur * 32768;
        const uint32_t Klb = Khb + 8192;
        const uint32_t Vhb = Khb + 16384;
        const uint32_t Vlb = Khb + 24576;

        float sacc[8][4] = {};
        #pragma unroll
        for (int ks = 0; ks < 4; ks++) {
            #pragma unroll
            for (int nt2 = 0; nt2 < 4; nt2++) {
                uint32_t brow = nt2 * 16 + (g >> 1) * 8 + r;
                uint32_t koff = ((ks * 2 + (g & 1)) ^ r) << 4;
                uint32_t t[4];
                ldm_x4(t, Khb + brow * 128 + koff);
                mma_bf16(sacc[2 * nt2],     qf[0][ks], t + 0);
                mma_bf16(sacc[2 * nt2 + 1], qf[0][ks], t + 2);
                mma_bf16(sacc[2 * nt2],     qf[1][ks], t + 0);
                mma_bf16(sacc[2 * nt2 + 1], qf[1][ks], t + 2);
                uint32_t u[4];
                ldm_x4(u, Klb + brow * 128 + koff);
                mma_bf16(sacc[2 * nt2],     qf[0][ks], u + 0);
                mma_bf16(sacc[2 * nt2 + 1], qf[0][ks], u + 2);
            }
        }

        float mx0 = m0, mx1 = m1;
        #pragma unroll
        for (int nt = 0; nt < 8; nt++) {
            mx0 = fmaxf(mx0, fmaxf(sacc[nt][0], sacc[nt][1]));
            mx1 = fmaxf(mx1, fmaxf(sacc[nt][2], sacc[nt][3]));
        }
        mx0 = fmaxf(mx0, __shfl_xor_sync(0xffffffffu, mx0, 1));
        mx0 = fmaxf(mx0, __shfl_xor_sync(0xffffffffu, mx0, 2));
        mx1 = fmaxf(mx1, __shfl_xor_sync(0xffffffffu, mx1, 1));
        mx1 = fmaxf(mx1, __shfl_xor_sync(0xffffffffu, mx1, 2));
        float al0 = __expf(m0 - mx0), al1 = __expf(m1 - mx1);
        m0 = mx0; m1 = mx1;
        float s0 = 0.0f, s1 = 0.0f;
        #pragma unroll
        for (int nt = 0; nt < 8; nt++) {
            sacc[nt][0] = __expf(sacc[nt][0] - m0);
            sacc[nt][1] = __expf(sacc[nt][1] - m0);
            sacc[nt][2] = __expf(sacc[nt][2] - m1);
            sacc[nt][3] = __expf(sacc[nt][3] - m1);
            s0 += sacc[nt][0] + sacc[nt][1];
            s1 += sacc[nt][2] + sacc[nt][3];
        }
        s0 += __shfl_xor_sync(0xffffffffu, s0, 1);
        s0 += __shfl_xor_sync(0xffffffffu, s0, 2);
        s1 += __shfl_xor_sync(0xffffffffu, s1, 1);
        s1 += __shfl_xor_sync(0xffffffffu, s1, 2);
        l0 = l0 * al0 + s0;
        l1 = l1 * al1 + s1;
        #pragma unroll
        for (int nt = 0; nt < 8; nt++) {
            oacc[nt][0] *= al0; oacc[nt][1] *= al0;
            oacc[nt][2] *= al1; oacc[nt][3] *= al1;
        }

        #pragma unroll
        for (int kk = 0; kk < 4; kk++) {
            uint32_t ah[4], al_[4];
            split_pair(sacc[2 * kk][0],     sacc[2 * kk][1],     ah[0], al_[0]);
            split_pair(sacc[2 * kk][2],     sacc[2 * kk][3],     ah[1], al_[1]);
            split_pair(sacc[2 * kk + 1][0], sacc[2 * kk + 1][1], ah[2], al_[2]);
            split_pair(sacc[2 * kk + 1][2], sacc[2 * kk + 1][3], ah[3], al_[3]);
            uint32_t key = kk * 16 + (g & 1) * 8 + r;
            #pragma unroll
            for (int nt2 = 0; nt2 < 4; nt2++) {
                uint32_t doff = (((nt2 * 2 + (g >> 1)) ^ r) << 4);
                uint32_t vb[4];
                ldm_x4_t(vb, Vhb + key * 128 + doff);
                mma_bf16(oacc[2 * nt2],     ah,  vb + 0);
                mma_bf16(oacc[2 * nt2 + 1], ah,  vb + 2);
                mma_bf16(oacc[2 * nt2],     al_, vb + 0);
                mma_bf16(oacc[2 * nt2 + 1], al_, vb + 2);
                uint32_t vc[4];
                ldm_x4_t(vc, Vlb + key * 128 + doff);
                mma_bf16(oacc[2 * nt2],     ah,  vc + 0);
                mma_bf16(oacc[2 * nt2 + 1], ah,  vc + 2);
            }
        }
        __syncthreads();
    }

    const int b_ = bh / NH, h_ = bh % NH;
    const int row0 = q0 + warp * 16 + (lane >> 2);
    const int col = (lane & 3) * 2;
    const float i0 = 1.0f / l0, i1 = 1.0f / l1;
    #pragma unroll
    for (int half = 0; half < 2; half++) {
        int srow = row0 + half * 8;
        __nv_bfloat16* arow = actx + (size_t)(b_ * SEQ + srow) * KS2;
        float inv = half ? i1 : i0;
        #pragma unroll
        for (int nt = 0; nt < 8; nt++) {
            int d = h_ * 64 + nt * 8 + col;
            float v0 = oacc[nt][half * 2 + 0] * inv;
            float v1 = oacc[nt][half * 2 + 1] * inv;
            __nv_bfloat16 h0 = __float2bfloat16(v0), h1 = __float2bfloat16(v1);
            __nv_bfloat162 hi2, lo2;
            hi2.x = h0; hi2.y = h1;
            lo2.x = __float2bfloat16(v0 - __bfloat162float(h0));
            lo2.y = __float2bfloat16(v1 - __bfloat162float(h1));
            *(__nv_bfloat162*)(arow + d) = hi2;
            *(__nv_bfloat162*)(arow + 1024 + d) = lo2;
        }
    }
}

extern "C" void kernel_launch(void* const* d_in, const int* in_sizes, int n_in,
                              void* d_out, int out_size)
{
    const float* query = (const float*)d_in[0];
    const float* key   = (const float*)d_in[1];
    const float* value = (const float*)d_in[2];
    const float* Wq = (const float*)d_in[3];
    const float* bq = (const float*)d_in[4];
    const float* Wk = (const float*)d_in[5];
    const float* bk = (const float*)d_in[6];
    const float* Wv = (const float*)d_in[7];
    const float* bv = (const float*)d_in[8];
    const float* Wo = (const float*)d_in[9];
    const float* bo = (const float*)d_in[10];
    float* out = (float*)d_out;

    __nv_bfloat16 *a0, *a1, *a2, *b0, *b1, *b2, *qh, *ql, *kh, *kl, *vh, *vl;
    cudaGetSymbolAddress((void**)&a0, g_A0);
    cudaGetSymbolAddress((void**)&a1, g_A1);
    cudaGetSymbolAddress((void**)&a2, g_A2);
    cudaGetSymbolAddress((void**)&b0, g_B0);
    cudaGetSymbolAddress((void**)&b1, g_B1);
    cudaGetSymbolAddress((void**)&b2, g_B2);
    cudaGetSymbolAddress((void**)&qh, g_Qh);
    cudaGetSymbolAddress((void**)&ql, g_Ql);
    cudaGetSymbolAddress((void**)&kh, g_Kh);
    cudaGetSymbolAddress((void**)&kl, g_Kl);
    cudaGetSymbolAddress((void**)&vh, g_Vh);
    cudaGetSymbolAddress((void**)&vl, g_Vl);

    cudaFuncSetAttribute(gemm_mma_kernel,
                         cudaFuncAttributeMaxDynamicSharedMemorySize, SMEM_GEMM);
    cudaFuncSetAttribute(attn_mma_kernel,
                         cudaFuncAttributeMaxDynamicSharedMemorySize, SMEM_ATTN);

    int blkA3 = (3 * MTOT * (HID / 2) + 255) / 256;
    int blkB3 = (3 * HID * (HID / 2) + 255) / 256;
    int blkB1 = (HID * (HID / 2) + 255) / 256;
    split3_kernel<<<blkA3, 256>>>(query, key, value, a0, a1, a2, MTOT);
    split3_kernel<<<blkB3, 256>>>(Wq, Wk, Wv, b0, b1, b2, HID);

    GemmArgs pa = {};
    pa.A[0] = a0; pa.A[1] = a1; pa.A[2] = a2;
    pa.B[0] = b0; pa.B[1] = b1; pa.B[2] = b2;
    pa.bias[0] = bq; pa.bias[1] = bk; pa.bias[2] = bv;
    pa.oh[0] = qh; pa.oh[1] = kh; pa.oh[2] = vh;
    pa.ol[0] = ql; pa.ol[1] = kl; pa.ol[2] = vl;
    pa.scale[0] = 0.125f; pa.scale[1] = 1.0f; pa.scale[2] = 1.0f;
    pa.out = nullptr; pa.mode = 1;
    gemm_mma_kernel<<<dim3(HID / GN, MTOT / GM, 3), 128, SMEM_GEMM>>>(pa);

    // Wo split into b1 (only `per` blocks launched, so which==0 for all threads)
    split3_kernel<<<blkB1, 256>>>(Wo, Wo, Wo, b1, b1, b1, HID);

    attn_mma_kernel<<<dim3(SEQ / 128, BATCH * NH), 256, SMEM_ATTN>>>(a0);

    GemmArgs oa = {};
    oa.A[0] = a0; oa.B[0] = b1; oa.bias[0] = bo;
    oa.scale[0] = 1.0f; oa.out = out; oa.mode = 0;
    gemm_mma_kernel<<<dim3(HID / GN, MTOT / GM, 1), 128, SMEM_GEMM>>>(oa);
}